// round 13
// baseline (speedup 1.0000x reference)
#include <cuda_runtime.h>
#include <cuda_fp16.h>
#include <cstdint>
#include <cstddef>

// Problem constants
#define BATCH   16
#define N_TOK   1024
#define DIM     512
#define NHEAD   8
#define KHOPS   5
#define HD      64
#define M_ROWS  (BATCH * N_TOK)    // 16384
#define QKV_N   (3 * DIM)          // 1536
#define SCALE_F 0.125f
#define LOG2E   1.4426950408889634f
#define QSCALE  (SCALE_F * LOG2E)   // folded: logits in log2 units

// ---------------------------------------------------------------------------
// Scratch (module-scope device globals; no runtime allocation)
// ---------------------------------------------------------------------------
__device__ __half g_bias[(size_t)NHEAD * N_TOK * N_TOK];  // hop bias * log2e (fp16)
__device__ __half g_xh[(size_t)M_ROWS * DIM];             // x rounded
__device__ __half g_aoh[(size_t)M_ROWS * DIM];            // attn out (fp16)
__device__ __half g_wqh[(size_t)QKV_N * DIM];             // Wqkv rounded
__device__ __half g_wph[(size_t)DIM * DIM];               // Wproj rounded
#define KVSZ ((size_t)BATCH * NHEAD * N_TOK * HD)
__device__ __half g_qh[KVSZ];                   // Q * scale * log2e [bh][tok][64]
__device__ __half g_kh[KVSZ];                   // K                 [bh][tok][64]
__device__ __half g_vth[KVSZ];                  // V^T               [bh][d][tok]

// ---------------------------------------------------------------------------
// helpers
// ---------------------------------------------------------------------------
// exp2 of two fp32 values (clamped) -> packed fp16x2, single MUFU op
__device__ __forceinline__ uint32_t ex2h2(float x, float y) {
    __half2 hv = __floats2half2_rn(fminf(x, 14.f), fminf(y, 14.f));
    uint32_t r, in = *reinterpret_cast<uint32_t*>(&hv);
    asm("ex2.approx.f16x2 %0, %1;" : "=r"(r) : "r"(in));
    return r;
}

__device__ __forceinline__ void mma16816(float* c, const uint32_t* a, const uint32_t* b) {
    asm volatile(
        "mma.sync.aligned.m16n8k16.row.col.f32.f16.f16.f32 "
        "{%0,%1,%2,%3}, {%4,%5,%6,%7}, {%8,%9}, {%0,%1,%2,%3};"
        : "+f"(c[0]), "+f"(c[1]), "+f"(c[2]), "+f"(c[3])
        : "r"(a[0]), "r"(a[1]), "r"(a[2]), "r"(a[3]), "r"(b[0]), "r"(b[1]));
}

__device__ __forceinline__ void ldsm4(uint32_t& r0, uint32_t& r1, uint32_t& r2,
                                      uint32_t& r3, uint32_t addr) {
    asm volatile("ldmatrix.sync.aligned.m8n8.x4.shared.b16 {%0,%1,%2,%3}, [%4];"
                 : "=r"(r0), "=r"(r1), "=r"(r2), "=r"(r3) : "r"(addr));
}

__device__ __forceinline__ void cp16(uint32_t dst, const void* src) {
    asm volatile("cp.async.cg.shared.global [%0], [%1], 16;" :: "r"(dst), "l"(src));
}
#define CP_COMMIT() asm volatile("cp.async.commit_group;")
#define CP_WAIT(n)  asm volatile("cp.async.wait_group %0;" :: "n"(n))

// ---------------------------------------------------------------------------
// fused round: fp32 -> fp16 for x | Wqkv | Wproj in one launch
// ---------------------------------------------------------------------------
#define N4_X  (M_ROWS * DIM / 4)          // 2097152
#define N4_WQ (QKV_N * DIM / 4)           // 196608
#define N4_WP (DIM * DIM / 4)             // 65536
#define N4_ALL (N4_X + N4_WQ + N4_WP)

__global__ void round_all(const float4* __restrict__ x,
                          const float4* __restrict__ wq,
                          const float4* __restrict__ wp) {
    int i = blockIdx.x * blockDim.x + threadIdx.x;
    if (i >= N4_ALL) return;
    const float4* src;
    uint2* dst;
    int k;
    if (i < N4_X) {
        src = x;  dst = reinterpret_cast<uint2*>(g_xh);  k = i;
    } else if (i < N4_X + N4_WQ) {
        src = wq; dst = reinterpret_cast<uint2*>(g_wqh); k = i - N4_X;
    } else {
        src = wp; dst = reinterpret_cast<uint2*>(g_wph); k = i - N4_X - N4_WQ;
    }
    float4 v = src[k];
    __half2 p0 = __floats2half2_rn(v.x, v.y);
    __half2 p1 = __floats2half2_rn(v.z, v.w);
    dst[k] = make_uint2(*reinterpret_cast<uint32_t*>(&p0), *reinterpret_cast<uint32_t*>(&p1));
}

// ---------------------------------------------------------------------------
// hop-bias precompute -> fp16, pre-multiplied by log2e
// ---------------------------------------------------------------------------
__global__ void bias_kernel(const float* __restrict__ Hstack,
                            const float* __restrict__ hop_logits,
                            const float* __restrict__ rel_alpha) {
    __shared__ float ws[NHEAD][KHOPS];
    if (threadIdx.x == 0) {
        for (int h = 0; h < NHEAD; h++) {
            float mx = -1e30f;
            for (int k = 0; k < KHOPS; k++) mx = fmaxf(mx, hop_logits[h * KHOPS + k]);
            float e[KHOPS]; float s = 0.f;
            for (int k = 0; k < KHOPS; k++) { e[k] = __expf(hop_logits[h * KHOPS + k] - mx); s += e[k]; }
            float a = rel_alpha[h] * LOG2E / s;
            for (int k = 0; k < KHOPS; k++) ws[h][k] = e[k] * a;
        }
    }
    __syncthreads();

    const int total4 = N_TOK * N_TOK / 4;
    int idx = blockIdx.x * blockDim.x + threadIdx.x;
    if (idx >= total4) return;

    float4 hv[KHOPS];
#pragma unroll
    for (int k = 0; k < KHOPS; k++)
        hv[k] = reinterpret_cast<const float4*>(Hstack)[(size_t)k * total4 + idx];

#pragma unroll
    for (int h = 0; h < NHEAD; h++) {
        float4 o = make_float4(0.f, 0.f, 0.f, 0.f);
#pragma unroll
        for (int k = 0; k < KHOPS; k++) {
            float w = ws[h][k];
            o.x += w * hv[k].x; o.y += w * hv[k].y;
            o.z += w * hv[k].z; o.w += w * hv[k].w;
        }
        __half2 p0 = __floats2half2_rn(o.x, o.y);
        __half2 p1 = __floats2half2_rn(o.z, o.w);
        reinterpret_cast<uint2*>(g_bias)[(size_t)h * total4 + idx] =
            make_uint2(*reinterpret_cast<uint32_t*>(&p0), *reinterpret_cast<uint32_t*>(&p1));
    }
}

// ---------------------------------------------------------------------------
// HMMA fp16 GEMM (1-term). MODE 0: fp32 store + bias (proj).
// MODE 1: QKV epilogue -> g_qh/kh/vth. 128x128 tile, BK=32, 4-stage cp.async.
// ---------------------------------------------------------------------------
#define BK  32
#define AKP 40
#define GEMM_SMEM (8 * 128 * AKP * 2)  // 81920 B

template <int MODE>
__global__ __launch_bounds__(256, 2)
void gemm_mma(const __half* __restrict__ Ah, const __half* __restrict__ Wh,
              float* __restrict__ C, int Ncols, const float* __restrict__ biasv) {
    extern __shared__ __half gsm[];
    const int tid = threadIdx.x;
    const int wid = tid >> 5, lane = tid & 31;
    const int g = lane >> 2, t4 = lane & 3;
    const int wm = (wid >> 1) * 32, wn = (wid & 1) * 64;
    const int m0 = blockIdx.y * 128, n0 = blockIdx.x * 128;
    const uint32_t smb = (uint32_t)__cvta_generic_to_shared(gsm);

    const int r0 = tid >> 2,         c0e = (tid & 3) * 8;
    const int r1 = (tid + 256) >> 2, c1e = ((tid + 256) & 3) * 8;

    float acc[2][8][4];
#pragma unroll
    for (int i = 0; i < 2; i++)
#pragma unroll
        for (int j = 0; j < 8; j++)
#pragma unroll
            for (int r = 0; r < 4; r++) acc[i][j][r] = 0.f;

    auto issue = [&](int st, int c) {
        const int k0 = c * BK;
        cp16(smb + 2u * (st * 5120 + r0 * AKP + c0e),
             Ah + (size_t)(m0 + r0) * DIM + k0 + c0e);
        cp16(smb + 2u * (st * 5120 + r1 * AKP + c1e),
             Ah + (size_t)(m0 + r1) * DIM + k0 + c1e);
        cp16(smb + 2u * (20480 + st * 5120 + r0 * AKP + c0e),
             Wh + (size_t)(n0 + r0) * DIM + k0 + c0e);
        cp16(smb + 2u * (20480 + st * 5120 + r1 * AKP + c1e),
             Wh + (size_t)(n0 + r1) * DIM + k0 + c1e);
    };

    issue(0, 0); CP_COMMIT();
    issue(1, 1); CP_COMMIT();
    issue(2, 2); CP_COMMIT();

    const int NCHUNK = 16;
    const int lrow = lane & 15, lcol = (lane >> 4) * 8;

    for (int c = 0; c < NCHUNK; c++) {
        CP_WAIT(2);
        __syncthreads();
        const int st = c & 3;
        const uint32_t abase = smb + 2u * (st * 5120);
        const uint32_t bbase = smb + 2u * (20480 + st * 5120);
#pragma unroll
        for (int kk = 0; kk < BK; kk += 16) {
            uint32_t a[2][4];
#pragma unroll
            for (int i = 0; i < 2; i++)
                ldsm4(a[i][0], a[i][1], a[i][2], a[i][3],
                      abase + 2u * ((wm + i * 16 + lrow) * AKP + kk + lcol));
#pragma unroll
            for (int jb = 0; jb < 4; jb++) {
                uint32_t q0, q1, q2, q3;
                ldsm4(q0, q1, q2, q3,
                      bbase + 2u * ((wn + jb * 16 + lrow) * AKP + kk + lcol));
                uint32_t b0[2] = {q0, q2}, b1[2] = {q1, q3};
                mma16816(acc[0][2 * jb],     a[0], b0);
                mma16816(acc[1][2 * jb],     a[1], b0);
                mma16816(acc[0][2 * jb + 1], a[0], b1);
                mma16816(acc[1][2 * jb + 1], a[1], b1);
            }
        }
        if (c + 3 < NCHUNK) issue((c + 3) & 3, c + 3);
        CP_COMMIT();
    }

    if (MODE == 0) {
#pragma unroll
        for (int i = 0; i < 2; i++) {
#pragma unroll
            for (int j = 0; j < 8; j++) {
                int col = n0 + wn + j * 8 + t4 * 2;
                float bx = biasv[col], by = biasv[col + 1];
                int row0 = m0 + wm + i * 16 + g;
                float2 v0 = make_float2(acc[i][j][0] + bx, acc[i][j][1] + by);
                float2 v1 = make_float2(acc[i][j][2] + bx, acc[i][j][3] + by);
                *reinterpret_cast<float2*>(C + (size_t)row0 * Ncols + col) = v0;
                *reinterpret_cast<float2*>(C + (size_t)(row0 + 8) * Ncols + col) = v1;
            }
        }
    } else {
        const int b = m0 >> 10;
#pragma unroll
        for (int i = 0; i < 2; i++) {
            const int tokA = (m0 & 1023) + wm + i * 16 + g;
            const int tokB = tokA + 8;
#pragma unroll
            for (int j = 0; j < 8; j++) {
                const int col = n0 + wn + j * 8 + t4 * 2;
                if (n0 < 512) {               // ---- Q: scale*log2e + round ----
                    const int hh = col >> 6, d = col & 63;
                    const size_t oA = (((size_t)(b * NHEAD + hh) << 10) + tokA) * HD + d;
                    const size_t oB = (((size_t)(b * NHEAD + hh) << 10) + tokB) * HD + d;
                    __half2 p0 = __floats2half2_rn(acc[i][j][0] * QSCALE, acc[i][j][1] * QSCALE);
                    __half2 p1 = __floats2half2_rn(acc[i][j][2] * QSCALE, acc[i][j][3] * QSCALE);
                    *reinterpret_cast<__half2*>(g_qh + oA) = p0;
                    *reinterpret_cast<__half2*>(g_qh + oB) = p1;
                } else if (n0 < 1024) {       // ---- K: round ----
                    const int c2 = col - 512;
                    const int hh = c2 >> 6, d = c2 & 63;
                    const size_t oA = (((size_t)(b * NHEAD + hh) << 10) + tokA) * HD + d;
                    const size_t oB = (((size_t)(b * NHEAD + hh) << 10) + tokB) * HD + d;
                    __half2 p0 = __floats2half2_rn(acc[i][j][0], acc[i][j][1]);
                    __half2 p1 = __floats2half2_rn(acc[i][j][2], acc[i][j][3]);
                    *reinterpret_cast<__half2*>(g_kh + oA) = p0;
                    *reinterpret_cast<__half2*>(g_kh + oB) = p1;
                } else {                      // ---- V: round + transpose ----
                    const int c2 = col - 1024;
                    const int hh = c2 >> 6, d = c2 & 63;
                    const size_t base = ((size_t)(b * NHEAD + hh) * HD + d) << 10;
                    g_vth[base + tokA]        = __float2half_rn(acc[i][j][0]);
                    g_vth[base + 1024 + tokA] = __float2half_rn(acc[i][j][1]);
                    g_vth[base + tokB]        = __float2half_rn(acc[i][j][2]);
                    g_vth[base + 1024 + tokB] = __float2half_rn(acc[i][j][3]);
                }
            }
        }
    }
}

// ---------------------------------------------------------------------------
// HMMA fp16 flash-attention, fixed-reference log2 softmax.
// Q fragments hoisted to registers; bias prefetched per chunk ahead of S-mma.
// Grid (N/128, H, B), 256 thr, 2 CTAs/SM.
// ---------------------------------------------------------------------------
#define QSK 72
#define VSK 72
#define QH_OFF 0
#define KOFF(st)  (9216 + (st) * 4608)
#define VTOFF(st) (18432 + (st) * 4608)
#define ATTN_SMEM (27648 * 2)   // 55296 B

__global__ __launch_bounds__(256, 2)
void attn_mma() {
    extern __shared__ __half sb[];
    const int b = blockIdx.z, h = blockIdx.y, r0 = blockIdx.x * 128;
    const int tid = threadIdx.x;
    const int wid = tid >> 5, lane = tid & 31;
    const int g = lane >> 2, t4 = lane & 3;
    const int wm = wid * 16;
    const int bh = b * NHEAD + h;
    const uint32_t smb = (uint32_t)__cvta_generic_to_shared(sb);
    const int lrow = lane & 15, lcol = (lane >> 4) * 8;

    const __half* Qhg  = g_qh  + ((size_t)bh << 10) * HD;
    const __half* Khg  = g_kh  + ((size_t)bh << 10) * HD;
    const __half* Vthg = g_vth + ((size_t)bh * HD << 10);
    const __half* Bg = g_bias + ((size_t)(h * N_TOK + r0)) * N_TOK;
    const __half* BgA = Bg + (size_t)(wm + g) * N_TOK + t4 * 2;       // row A base
    const __half* BgB = Bg + (size_t)(wm + g + 8) * N_TOK + t4 * 2;   // row B base

    // Q tile via cp.async (128 x 64)
#pragma unroll
    for (int s = 0; s < 4; s++) {
        const int id = tid + s * 256;
        const int r = id >> 3, c = (id & 7) * 8;
        cp16(smb + 2u * (QH_OFF + r * QSK + c), Qhg + (size_t)(r0 + r) * HD + c);
    }

    auto issue = [&](int st, int c0) {
#pragma unroll
        for (int s = 0; s < 2; s++) {
            const int id = tid + s * 256;
            const int r = id >> 3, c = (id & 7) * 8;
            cp16(smb + 2u * (KOFF(st) + r * QSK + c), Khg + (size_t)(c0 + r) * HD + c);
            cp16(smb + 2u * (VTOFF(st) + r * VSK + c), Vthg + ((size_t)r << 10) + c0 + c);
        }
    };

    issue(0, 0); CP_COMMIT();

    float lacc[4] = {0.f, 0.f, 0.f, 0.f};
    float O[8][4];
#pragma unroll
    for (int j = 0; j < 8; j++)
#pragma unroll
        for (int r = 0; r < 4; r++) O[j][r] = 0.f;

    uint32_t qf[4][4];          // hoisted Q fragments (chunk-invariant)
    const uint32_t ones2[2] = {0x3C003C00u, 0x3C003C00u};

    for (int cc = 0; cc < 16; cc++) {
        const int c0 = cc * 64;

        // prefetch bias for this chunk (L2) — overlaps cp.async wait + S-mma
        uint32_t bvA[8], bvB[8];
#pragma unroll
        for (int j = 0; j < 8; j++) {
            bvA[j] = *reinterpret_cast<const uint32_t*>(BgA + c0 + j * 8);
            bvB[j] = *reinterpret_cast<const uint32_t*>(BgB + c0 + j * 8);
        }

        if (cc + 1 < 16) { issue((cc + 1) & 1, (cc + 1) * 64); CP_COMMIT(); CP_WAIT(1); }
        else             { CP_WAIT(0); }
        __syncthreads();
        const int st = cc & 1;

        if (cc == 0) {
#pragma unroll
            for (int kt = 0; kt < 4; kt++)
                ldsm4(qf[kt][0], qf[kt][1], qf[kt][2], qf[kt][3],
                      smb + 2u * (QH_OFF + (wm + lrow) * QSK + kt * 16 + lcol));
        }

        // ---- S = Qh Kh^T  (log2 units) ----
        float S[8][4];
#pragma unroll
        for (int j = 0; j < 8; j++)
#pragma unroll
            for (int r = 0; r < 4; r++) S[j][r] = 0.f;

#pragma unroll
        for (int kt = 0; kt < 4; kt++) {
#pragma unroll
            for (int jb = 0; jb < 4; jb++) {
                uint32_t q0, q1, q2, q3;
                ldsm4(q0, q1, q2, q3,
                      smb + 2u * (KOFF(st) + (jb * 16 + lrow) * QSK + kt * 16 + lcol));
                uint32_t b0[2] = {q0, q2}, b1[2] = {q1, q3};
                mma16816(S[2 * jb],     qf[kt], b0);
                mma16816(S[2 * jb + 1], qf[kt], b1);
            }
        }

        // ---- + bias (prefetched, already *log2e) ----
#pragma unroll
        for (int j = 0; j < 8; j++) {
            float2 bv0 = __half22float2(*reinterpret_cast<const __half2*>(&bvA[j]));
            float2 bv1 = __half22float2(*reinterpret_cast<const __half2*>(&bvB[j]));
            S[j][0] += bv0.x; S[j][1] += bv0.y;
            S[j][2] += bv1.x; S[j][3] += bv1.y;
        }

        // ---- P = ex2(S) fp16; l += P*1; O += P*Vh ----
#pragma unroll
        for (int kt = 0; kt < 4; kt++) {
            uint32_t ph[4];
            ph[0] = ex2h2(S[2 * kt][0],     S[2 * kt][1]);
            ph[1] = ex2h2(S[2 * kt][2],     S[2 * kt][3]);
            ph[2] = ex2h2(S[2 * kt + 1][0], S[2 * kt + 1][1]);
            ph[3] = ex2h2(S[2 * kt + 1][2], S[2 * kt + 1][3]);
            mma16816(lacc, ph, ones2);
#pragma unroll
            for (int jb = 0; jb < 4; jb++) {
                uint32_t h0, h1, h2, h3;
                ldsm4(h0, h1, h2, h3,
                      smb + 2u * (VTOFF(st) + (jb * 16 + lrow) * VSK + kt * 16 + lcol));
                uint32_t bh0[2] = {h0, h2}, bh1[2] = {h1, h3};
                mma16816(O[2 * jb],     ph, bh0);
                mma16816(O[2 * jb + 1], ph, bh1);
            }
        }
        __syncthreads();
    }

    // ---- normalize + write fp16 proj operand ----
    float inv0 = 1.0f / lacc[0], inv1 = 1.0f / lacc[2];
    const int row = r0 + wm + g;
    size_t base0 = ((size_t)(b * N_TOK) + row) * DIM + h * HD;
    size_t base1 = base0 + (size_t)8 * DIM;
#pragma unroll
    for (int j = 0; j < 8; j++) {
        const int col = j * 8 + t4 * 2;
        __half2 v0 = __floats2half2_rn(O[j][0] * inv0, O[j][1] * inv0);
        __half2 v1 = __floats2half2_rn(O[j][2] * inv1, O[j][3] * inv1);
        *reinterpret_cast<__half2*>(g_aoh + base0 + col) = v0;
        *reinterpret_cast<__half2*>(g_aoh + base1 + col) = v1;
    }
}

// ---------------------------------------------------------------------------
// Launch
// ---------------------------------------------------------------------------
extern "C" void kernel_launch(void* const* d_in, const int* in_sizes, int n_in,
                              void* d_out, int out_size) {
    const float* x          = (const float*)d_in[0];
    const float* Hstack     = (const float*)d_in[1];
    const float* hop_logits = (const float*)d_in[2];
    const float* rel_alpha  = (const float*)d_in[3];
    const float* Wqkv       = (const float*)d_in[4];
    const float* Wproj      = (const float*)d_in[5];
    const float* bproj      = (const float*)d_in[6];
    float* out = (float*)d_out;

    __half *xh, *aoh, *wqh, *wph;
    cudaGetSymbolAddress((void**)&xh, g_xh);
    cudaGetSymbolAddress((void**)&aoh, g_aoh);
    cudaGetSymbolAddress((void**)&wqh, g_wqh);
    cudaGetSymbolAddress((void**)&wph, g_wph);

    static bool attr_done = false;
    if (!attr_done) {
        cudaFuncSetAttribute(attn_mma, cudaFuncAttributeMaxDynamicSharedMemorySize, ATTN_SMEM);
        cudaFuncSetAttribute((const void*)gemm_mma<0>, cudaFuncAttributeMaxDynamicSharedMemorySize, GEMM_SMEM);
        cudaFuncSetAttribute((const void*)gemm_mma<1>, cudaFuncAttributeMaxDynamicSharedMemorySize, GEMM_SMEM);
        attr_done = true;
    }

    // 1) hop bias (fp16, *log2e)
    bias_kernel<<<(N_TOK * N_TOK / 4 + 255) / 256, 256>>>(Hstack, hop_logits, rel_alpha);

    // 2) round all operands to fp16 (single fused launch)
    round_all<<<(N4_ALL + 255) / 256, 256>>>(
        (const float4*)x, (const float4*)Wqkv, (const float4*)Wproj);

    // 3) QKV projection with fused attention-prep epilogue
    gemm_mma<1><<<dim3(QKV_N / 128, M_ROWS / 128), 256, GEMM_SMEM>>>(
        xh, wqh, nullptr, QKV_N, nullptr);

    // 4) fp16 flash attention (fixed-reference log2 softmax) -> g_aoh
    attn_mma<<<dim3(N_TOK / 128, NHEAD, BATCH), 256, ATTN_SMEM>>>();

    // 5) output projection + bias -> out
    gemm_mma<0><<<dim3(DIM / 128, M_ROWS / 128), 256, GEMM_SMEM>>>(
        aoh, wph, out, DIM, bproj);
}

// round 14
// speedup vs baseline: 1.0006x; 1.0006x over previous
#include <cuda_runtime.h>
#include <cuda_fp16.h>
#include <cstdint>
#include <cstddef>

// Problem constants
#define BATCH   16
#define N_TOK   1024
#define DIM     512
#define NHEAD   8
#define KHOPS   5
#define HD      64
#define M_ROWS  (BATCH * N_TOK)    // 16384
#define QKV_N   (3 * DIM)          // 1536
#define SCALE_F 0.125f
#define LOG2E   1.4426950408889634f
#define QSCALE  (SCALE_F * LOG2E)   // folded: logits in log2 units

// ---------------------------------------------------------------------------
// Scratch (module-scope device globals; no runtime allocation)
// ---------------------------------------------------------------------------
__device__ __half g_bias[(size_t)NHEAD * N_TOK * N_TOK];  // hop bias * log2e (fp16)
__device__ __half g_xh[(size_t)M_ROWS * DIM];             // x rounded
__device__ __half g_aoh[(size_t)M_ROWS * DIM];            // attn out (fp16)
__device__ __half g_wqh[(size_t)QKV_N * DIM];             // Wqkv rounded
__device__ __half g_wph[(size_t)DIM * DIM];               // Wproj rounded
#define KVSZ ((size_t)BATCH * NHEAD * N_TOK * HD)
__device__ __half g_qh[KVSZ];                   // Q * scale * log2e [bh][tok][64]
__device__ __half g_kh[KVSZ];                   // K                 [bh][tok][64]
__device__ __half g_vth[KVSZ];                  // V^T               [bh][d][tok]

// ---------------------------------------------------------------------------
// helpers
// ---------------------------------------------------------------------------
__device__ __forceinline__ uint32_t ex2h2(float x, float y) {
    __half2 hv = __floats2half2_rn(fminf(x, 14.f), fminf(y, 14.f));
    uint32_t r, in = *reinterpret_cast<uint32_t*>(&hv);
    asm("ex2.approx.f16x2 %0, %1;" : "=r"(r) : "r"(in));
    return r;
}

__device__ __forceinline__ void mma16816(float* c, const uint32_t* a, const uint32_t* b) {
    asm volatile(
        "mma.sync.aligned.m16n8k16.row.col.f32.f16.f16.f32 "
        "{%0,%1,%2,%3}, {%4,%5,%6,%7}, {%8,%9}, {%0,%1,%2,%3};"
        : "+f"(c[0]), "+f"(c[1]), "+f"(c[2]), "+f"(c[3])
        : "r"(a[0]), "r"(a[1]), "r"(a[2]), "r"(a[3]), "r"(b[0]), "r"(b[1]));
}

__device__ __forceinline__ void ldsm4(uint32_t& r0, uint32_t& r1, uint32_t& r2,
                                      uint32_t& r3, uint32_t addr) {
    asm volatile("ldmatrix.sync.aligned.m8n8.x4.shared.b16 {%0,%1,%2,%3}, [%4];"
                 : "=r"(r0), "=r"(r1), "=r"(r2), "=r"(r3) : "r"(addr));
}

__device__ __forceinline__ void cp16(uint32_t dst, const void* src) {
    asm volatile("cp.async.cg.shared.global [%0], [%1], 16;" :: "r"(dst), "l"(src));
}
#define CP_COMMIT() asm volatile("cp.async.commit_group;")
#define CP_WAIT(n)  asm volatile("cp.async.wait_group %0;" :: "n"(n))

// ---------------------------------------------------------------------------
// fused round: fp32 -> fp16 for x | Wqkv | Wproj in one launch
// ---------------------------------------------------------------------------
#define N4_X  (M_ROWS * DIM / 4)
#define N4_WQ (QKV_N * DIM / 4)
#define N4_WP (DIM * DIM / 4)
#define N4_ALL (N4_X + N4_WQ + N4_WP)

__global__ void round_all(const float4* __restrict__ x,
                          const float4* __restrict__ wq,
                          const float4* __restrict__ wp) {
    int i = blockIdx.x * blockDim.x + threadIdx.x;
    if (i >= N4_ALL) return;
    const float4* src;
    uint2* dst;
    int k;
    if (i < N4_X) {
        src = x;  dst = reinterpret_cast<uint2*>(g_xh);  k = i;
    } else if (i < N4_X + N4_WQ) {
        src = wq; dst = reinterpret_cast<uint2*>(g_wqh); k = i - N4_X;
    } else {
        src = wp; dst = reinterpret_cast<uint2*>(g_wph); k = i - N4_X - N4_WQ;
    }
    float4 v = src[k];
    __half2 p0 = __floats2half2_rn(v.x, v.y);
    __half2 p1 = __floats2half2_rn(v.z, v.w);
    dst[k] = make_uint2(*reinterpret_cast<uint32_t*>(&p0), *reinterpret_cast<uint32_t*>(&p1));
}

// ---------------------------------------------------------------------------
// hop-bias precompute -> fp16, pre-multiplied by log2e
// ---------------------------------------------------------------------------
__global__ void bias_kernel(const float* __restrict__ Hstack,
                            const float* __restrict__ hop_logits,
                            const float* __restrict__ rel_alpha) {
    __shared__ float ws[NHEAD][KHOPS];
    if (threadIdx.x == 0) {
        for (int h = 0; h < NHEAD; h++) {
            float mx = -1e30f;
            for (int k = 0; k < KHOPS; k++) mx = fmaxf(mx, hop_logits[h * KHOPS + k]);
            float e[KHOPS]; float s = 0.f;
            for (int k = 0; k < KHOPS; k++) { e[k] = __expf(hop_logits[h * KHOPS + k] - mx); s += e[k]; }
            float a = rel_alpha[h] * LOG2E / s;
            for (int k = 0; k < KHOPS; k++) ws[h][k] = e[k] * a;
        }
    }
    __syncthreads();

    const int total4 = N_TOK * N_TOK / 4;
    int idx = blockIdx.x * blockDim.x + threadIdx.x;
    if (idx >= total4) return;

    float4 hv[KHOPS];
#pragma unroll
    for (int k = 0; k < KHOPS; k++)
        hv[k] = reinterpret_cast<const float4*>(Hstack)[(size_t)k * total4 + idx];

#pragma unroll
    for (int h = 0; h < NHEAD; h++) {
        float4 o = make_float4(0.f, 0.f, 0.f, 0.f);
#pragma unroll
        for (int k = 0; k < KHOPS; k++) {
            float w = ws[h][k];
            o.x += w * hv[k].x; o.y += w * hv[k].y;
            o.z += w * hv[k].z; o.w += w * hv[k].w;
        }
        __half2 p0 = __floats2half2_rn(o.x, o.y);
        __half2 p1 = __floats2half2_rn(o.z, o.w);
        reinterpret_cast<uint2*>(g_bias)[(size_t)h * total4 + idx] =
            make_uint2(*reinterpret_cast<uint32_t*>(&p0), *reinterpret_cast<uint32_t*>(&p1));
    }
}

// ---------------------------------------------------------------------------
// HMMA fp16 GEMM (1-term). MODE 0: fp32 store + bias (proj).
// MODE 1: QKV epilogue -> g_qh/kh/vth. 128x128 tile, BK=32, 4-stage cp.async.
// ---------------------------------------------------------------------------
#define BK  32
#define AKP 40
#define GEMM_SMEM (8 * 128 * AKP * 2)  // 81920 B

template <int MODE>
__global__ __launch_bounds__(256, 2)
void gemm_mma(const __half* __restrict__ Ah, const __half* __restrict__ Wh,
              float* __restrict__ C, int Ncols, const float* __restrict__ biasv) {
    extern __shared__ __half gsm[];
    const int tid = threadIdx.x;
    const int wid = tid >> 5, lane = tid & 31;
    const int g = lane >> 2, t4 = lane & 3;
    const int wm = (wid >> 1) * 32, wn = (wid & 1) * 64;
    const int m0 = blockIdx.y * 128, n0 = blockIdx.x * 128;
    const uint32_t smb = (uint32_t)__cvta_generic_to_shared(gsm);

    const int r0 = tid >> 2,         c0e = (tid & 3) * 8;
    const int r1 = (tid + 256) >> 2, c1e = ((tid + 256) & 3) * 8;

    float acc[2][8][4];
#pragma unroll
    for (int i = 0; i < 2; i++)
#pragma unroll
        for (int j = 0; j < 8; j++)
#pragma unroll
            for (int r = 0; r < 4; r++) acc[i][j][r] = 0.f;

    auto issue = [&](int st, int c) {
        const int k0 = c * BK;
        cp16(smb + 2u * (st * 5120 + r0 * AKP + c0e),
             Ah + (size_t)(m0 + r0) * DIM + k0 + c0e);
        cp16(smb + 2u * (st * 5120 + r1 * AKP + c1e),
             Ah + (size_t)(m0 + r1) * DIM + k0 + c1e);
        cp16(smb + 2u * (20480 + st * 5120 + r0 * AKP + c0e),
             Wh + (size_t)(n0 + r0) * DIM + k0 + c0e);
        cp16(smb + 2u * (20480 + st * 5120 + r1 * AKP + c1e),
             Wh + (size_t)(n0 + r1) * DIM + k0 + c1e);
    };

    issue(0, 0); CP_COMMIT();
    issue(1, 1); CP_COMMIT();
    issue(2, 2); CP_COMMIT();

    const int NCHUNK = 16;
    const int lrow = lane & 15, lcol = (lane >> 4) * 8;

    for (int c = 0; c < NCHUNK; c++) {
        CP_WAIT(2);
        __syncthreads();
        const int st = c & 3;
        const uint32_t abase = smb + 2u * (st * 5120);
        const uint32_t bbase = smb + 2u * (20480 + st * 5120);
#pragma unroll
        for (int kk = 0; kk < BK; kk += 16) {
            uint32_t a[2][4];
#pragma unroll
            for (int i = 0; i < 2; i++)
                ldsm4(a[i][0], a[i][1], a[i][2], a[i][3],
                      abase + 2u * ((wm + i * 16 + lrow) * AKP + kk + lcol));
#pragma unroll
            for (int jb = 0; jb < 4; jb++) {
                uint32_t q0, q1, q2, q3;
                ldsm4(q0, q1, q2, q3,
                      bbase + 2u * ((wn + jb * 16 + lrow) * AKP + kk + lcol));
                uint32_t b0[2] = {q0, q2}, b1[2] = {q1, q3};
                mma16816(acc[0][2 * jb],     a[0], b0);
                mma16816(acc[1][2 * jb],     a[1], b0);
                mma16816(acc[0][2 * jb + 1], a[0], b1);
                mma16816(acc[1][2 * jb + 1], a[1], b1);
            }
        }
        if (c + 3 < NCHUNK) issue((c + 3) & 3, c + 3);
        CP_COMMIT();
    }

    if (MODE == 0) {
#pragma unroll
        for (int i = 0; i < 2; i++) {
#pragma unroll
            for (int j = 0; j < 8; j++) {
                int col = n0 + wn + j * 8 + t4 * 2;
                float bx = biasv[col], by = biasv[col + 1];
                int row0 = m0 + wm + i * 16 + g;
                float2 v0 = make_float2(acc[i][j][0] + bx, acc[i][j][1] + by);
                float2 v1 = make_float2(acc[i][j][2] + bx, acc[i][j][3] + by);
                *reinterpret_cast<float2*>(C + (size_t)row0 * Ncols + col) = v0;
                *reinterpret_cast<float2*>(C + (size_t)(row0 + 8) * Ncols + col) = v1;
            }
        }
    } else {
        const int b = m0 >> 10;
#pragma unroll
        for (int i = 0; i < 2; i++) {
            const int tokA = (m0 & 1023) + wm + i * 16 + g;
            const int tokB = tokA + 8;
#pragma unroll
            for (int j = 0; j < 8; j++) {
                const int col = n0 + wn + j * 8 + t4 * 2;
                if (n0 < 512) {               // ---- Q: scale*log2e + round ----
                    const int hh = col >> 6, d = col & 63;
                    const size_t oA = (((size_t)(b * NHEAD + hh) << 10) + tokA) * HD + d;
                    const size_t oB = (((size_t)(b * NHEAD + hh) << 10) + tokB) * HD + d;
                    __half2 p0 = __floats2half2_rn(acc[i][j][0] * QSCALE, acc[i][j][1] * QSCALE);
                    __half2 p1 = __floats2half2_rn(acc[i][j][2] * QSCALE, acc[i][j][3] * QSCALE);
                    *reinterpret_cast<__half2*>(g_qh + oA) = p0;
                    *reinterpret_cast<__half2*>(g_qh + oB) = p1;
                } else if (n0 < 1024) {       // ---- K: round ----
                    const int c2 = col - 512;
                    const int hh = c2 >> 6, d = c2 & 63;
                    const size_t oA = (((size_t)(b * NHEAD + hh) << 10) + tokA) * HD + d;
                    const size_t oB = (((size_t)(b * NHEAD + hh) << 10) + tokB) * HD + d;
                    __half2 p0 = __floats2half2_rn(acc[i][j][0], acc[i][j][1]);
                    __half2 p1 = __floats2half2_rn(acc[i][j][2], acc[i][j][3]);
                    *reinterpret_cast<__half2*>(g_kh + oA) = p0;
                    *reinterpret_cast<__half2*>(g_kh + oB) = p1;
                } else {                      // ---- V: round + transpose ----
                    const int c2 = col - 1024;
                    const int hh = c2 >> 6, d = c2 & 63;
                    const size_t base = ((size_t)(b * NHEAD + hh) * HD + d) << 10;
                    g_vth[base + tokA]        = __float2half_rn(acc[i][j][0]);
                    g_vth[base + 1024 + tokA] = __float2half_rn(acc[i][j][1]);
                    g_vth[base + tokB]        = __float2half_rn(acc[i][j][2]);
                    g_vth[base + 1024 + tokB] = __float2half_rn(acc[i][j][3]);
                }
            }
        }
    }
}

// ---------------------------------------------------------------------------
// HMMA fp16 flash-attention, fixed-reference log2 softmax.
// 128 threads / 4 warps; each warp owns 32 rows (two m16 fragments) so every
// K/V ldsm fragment feeds 2x the output rows (halved L1 traffic vs 8-warp).
// Grid (N/128, H, B), 2 CTAs/SM.
// ---------------------------------------------------------------------------
#define QSK 72
#define VSK 72
#define QH_OFF 0
#define KOFF(st)  (9216 + (st) * 4608)
#define VTOFF(st) (18432 + (st) * 4608)
#define ATTN_SMEM (27648 * 2)   // 55296 B

__global__ __launch_bounds__(128, 2)
void attn_mma() {
    extern __shared__ __half sb[];
    const int b = blockIdx.z, h = blockIdx.y, r0 = blockIdx.x * 128;
    const int tid = threadIdx.x;
    const int wid = tid >> 5, lane = tid & 31;
    const int g = lane >> 2, t4 = lane & 3;
    const int wm = wid * 32;                 // 32 rows per warp
    const int bh = b * NHEAD + h;
    const uint32_t smb = (uint32_t)__cvta_generic_to_shared(sb);
    const int lrow = lane & 15, lcol = (lane >> 4) * 8;

    const __half* Qhg  = g_qh  + ((size_t)bh << 10) * HD;
    const __half* Khg  = g_kh  + ((size_t)bh << 10) * HD;
    const __half* Vthg = g_vth + ((size_t)bh * HD << 10);
    const __half* Bg = g_bias + ((size_t)(h * N_TOK + r0)) * N_TOK;

    // Q tile via cp.async (128 x 64), 128 threads x 8 chunks
#pragma unroll
    for (int s = 0; s < 8; s++) {
        const int id = tid + s * 128;
        const int r = id >> 3, c = (id & 7) * 8;
        cp16(smb + 2u * (QH_OFF + r * QSK + c), Qhg + (size_t)(r0 + r) * HD + c);
    }

    auto issue = [&](int st, int c0) {
#pragma unroll
        for (int s = 0; s < 4; s++) {
            const int id = tid + s * 128;
            const int r = id >> 3, c = (id & 7) * 8;
            cp16(smb + 2u * (KOFF(st) + r * QSK + c), Khg + (size_t)(c0 + r) * HD + c);
            cp16(smb + 2u * (VTOFF(st) + r * VSK + c), Vthg + ((size_t)r << 10) + c0 + c);
        }
    };

    issue(0, 0); CP_COMMIT();

    float lacc0[4] = {0.f, 0.f, 0.f, 0.f};
    float lacc1[4] = {0.f, 0.f, 0.f, 0.f};
    float O0[8][4], O1[8][4];
#pragma unroll
    for (int j = 0; j < 8; j++)
#pragma unroll
        for (int r = 0; r < 4; r++) { O0[j][r] = 0.f; O1[j][r] = 0.f; }

    uint32_t qf[2][4][4];          // hoisted Q fragments (2 halves x 4 kt)
    const uint32_t ones2[2] = {0x3C003C00u, 0x3C003C00u};

    for (int cc = 0; cc < 16; cc++) {
        const int c0 = cc * 64;
        if (cc + 1 < 16) { issue((cc + 1) & 1, (cc + 1) * 64); CP_COMMIT(); CP_WAIT(1); }
        else             { CP_WAIT(0); }
        __syncthreads();
        const int st = cc & 1;

        if (cc == 0) {
#pragma unroll
            for (int hf = 0; hf < 2; hf++)
#pragma unroll
                for (int kt = 0; kt < 4; kt++)
                    ldsm4(qf[hf][kt][0], qf[hf][kt][1], qf[hf][kt][2], qf[hf][kt][3],
                          smb + 2u * (QH_OFF + (wm + hf * 16 + lrow) * QSK + kt * 16 + lcol));
        }

        // ---- S = Qh Kh^T for both row-halves (shared K fragments) ----
        float S0[8][4], S1[8][4];
#pragma unroll
        for (int j = 0; j < 8; j++)
#pragma unroll
            for (int r = 0; r < 4; r++) { S0[j][r] = 0.f; S1[j][r] = 0.f; }

#pragma unroll
        for (int kt = 0; kt < 4; kt++) {
#pragma unroll
            for (int jb = 0; jb < 4; jb++) {
                uint32_t q0, q1, q2, q3;
                ldsm4(q0, q1, q2, q3,
                      smb + 2u * (KOFF(st) + (jb * 16 + lrow) * QSK + kt * 16 + lcol));
                uint32_t b0[2] = {q0, q2}, b1[2] = {q1, q3};
                mma16816(S0[2 * jb],     qf[0][kt], b0);
                mma16816(S0[2 * jb + 1], qf[0][kt], b1);
                mma16816(S1[2 * jb],     qf[1][kt], b0);
                mma16816(S1[2 * jb + 1], qf[1][kt], b1);
            }
        }

        // ---- + bias (fp16, already *log2e) ----
#pragma unroll
        for (int j = 0; j < 8; j++) {
            const int cix = c0 + j * 8 + t4 * 2;
            float2 v;
            v = __half22float2(*reinterpret_cast<const __half2*>(Bg + (size_t)(wm + g) * N_TOK + cix));
            S0[j][0] += v.x; S0[j][1] += v.y;
            v = __half22float2(*reinterpret_cast<const __half2*>(Bg + (size_t)(wm + g + 8) * N_TOK + cix));
            S0[j][2] += v.x; S0[j][3] += v.y;
            v = __half22float2(*reinterpret_cast<const __half2*>(Bg + (size_t)(wm + 16 + g) * N_TOK + cix));
            S1[j][0] += v.x; S1[j][1] += v.y;
            v = __half22float2(*reinterpret_cast<const __half2*>(Bg + (size_t)(wm + 24 + g) * N_TOK + cix));
            S1[j][2] += v.x; S1[j][3] += v.y;
        }

        // ---- P = ex2(S) fp16; l += P*1 ----
        uint32_t ph0[4][4], ph1[4][4];
#pragma unroll
        for (int kt = 0; kt < 4; kt++) {
            ph0[kt][0] = ex2h2(S0[2 * kt][0],     S0[2 * kt][1]);
            ph0[kt][1] = ex2h2(S0[2 * kt][2],     S0[2 * kt][3]);
            ph0[kt][2] = ex2h2(S0[2 * kt + 1][0], S0[2 * kt + 1][1]);
            ph0[kt][3] = ex2h2(S0[2 * kt + 1][2], S0[2 * kt + 1][3]);
            mma16816(lacc0, ph0[kt], ones2);
            ph1[kt][0] = ex2h2(S1[2 * kt][0],     S1[2 * kt][1]);
            ph1[kt][1] = ex2h2(S1[2 * kt][2],     S1[2 * kt][3]);
            ph1[kt][2] = ex2h2(S1[2 * kt + 1][0], S1[2 * kt + 1][1]);
            ph1[kt][3] = ex2h2(S1[2 * kt + 1][2], S1[2 * kt + 1][3]);
            mma16816(lacc1, ph1[kt], ones2);
        }

        // ---- O += P Vh for both halves (shared V fragments) ----
#pragma unroll
        for (int kt = 0; kt < 4; kt++) {
#pragma unroll
            for (int jb = 0; jb < 4; jb++) {
                uint32_t h0, h1, h2, h3;
                ldsm4(h0, h1, h2, h3,
                      smb + 2u * (VTOFF(st) + (jb * 16 + lrow) * VSK + kt * 16 + lcol));
                uint32_t bh0[2] = {h0, h2}, bh1[2] = {h1, h3};
                mma16816(O0[2 * jb],     ph0[kt], bh0);
                mma16816(O0[2 * jb + 1], ph0[kt], bh1);
                mma16816(O1[2 * jb],     ph1[kt], bh0);
                mma16816(O1[2 * jb + 1], ph1[kt], bh1);
            }
        }
        __syncthreads();
    }

    // ---- normalize + write fp16 proj operand ----
    float i00 = 1.0f / lacc0[0], i01 = 1.0f / lacc0[2];
    float i10 = 1.0f / lacc1[0], i11 = 1.0f / lacc1[2];
    const int rowA = r0 + wm + g;
    size_t baseA = ((size_t)(b * N_TOK) + rowA) * DIM + h * HD;        // wm+g
    size_t baseB = baseA + (size_t)8 * DIM;                            // wm+g+8
    size_t baseC = baseA + (size_t)16 * DIM;                           // wm+16+g
    size_t baseD = baseA + (size_t)24 * DIM;                           // wm+24+g
#pragma unroll
    for (int j = 0; j < 8; j++) {
        const int col = j * 8 + t4 * 2;
        *reinterpret_cast<__half2*>(g_aoh + baseA + col) =
            __floats2half2_rn(O0[j][0] * i00, O0[j][1] * i00);
        *reinterpret_cast<__half2*>(g_aoh + baseB + col) =
            __floats2half2_rn(O0[j][2] * i01, O0[j][3] * i01);
        *reinterpret_cast<__half2*>(g_aoh + baseC + col) =
            __floats2half2_rn(O1[j][0] * i10, O1[j][1] * i10);
        *reinterpret_cast<__half2*>(g_aoh + baseD + col) =
            __floats2half2_rn(O1[j][2] * i11, O1[j][3] * i11);
    }
}

// ---------------------------------------------------------------------------
// Launch
// ---------------------------------------------------------------------------
extern "C" void kernel_launch(void* const* d_in, const int* in_sizes, int n_in,
                              void* d_out, int out_size) {
    const float* x          = (const float*)d_in[0];
    const float* Hstack     = (const float*)d_in[1];
    const float* hop_logits = (const float*)d_in[2];
    const float* rel_alpha  = (const float*)d_in[3];
    const float* Wqkv       = (const float*)d_in[4];
    const float* Wproj      = (const float*)d_in[5];
    const float* bproj      = (const float*)d_in[6];
    float* out = (float*)d_out;

    __half *xh, *aoh, *wqh, *wph;
    cudaGetSymbolAddress((void**)&xh, g_xh);
    cudaGetSymbolAddress((void**)&aoh, g_aoh);
    cudaGetSymbolAddress((void**)&wqh, g_wqh);
    cudaGetSymbolAddress((void**)&wph, g_wph);

    static bool attr_done = false;
    if (!attr_done) {
        cudaFuncSetAttribute(attn_mma, cudaFuncAttributeMaxDynamicSharedMemorySize, ATTN_SMEM);
        cudaFuncSetAttribute((const void*)gemm_mma<0>, cudaFuncAttributeMaxDynamicSharedMemorySize, GEMM_SMEM);
        cudaFuncSetAttribute((const void*)gemm_mma<1>, cudaFuncAttributeMaxDynamicSharedMemorySize, GEMM_SMEM);
        attr_done = true;
    }

    // 1) hop bias (fp16, *log2e)
    bias_kernel<<<(N_TOK * N_TOK / 4 + 255) / 256, 256>>>(Hstack, hop_logits, rel_alpha);

    // 2) round all operands to fp16 (single fused launch)
    round_all<<<(N4_ALL + 255) / 256, 256>>>(
        (const float4*)x, (const float4*)Wqkv, (const float4*)Wproj);

    // 3) QKV projection with fused attention-prep epilogue
    gemm_mma<1><<<dim3(QKV_N / 128, M_ROWS / 128), 256, GEMM_SMEM>>>(
        xh, wqh, nullptr, QKV_N, nullptr);

    // 4) fp16 flash attention (fixed-reference log2 softmax) -> g_aoh
    attn_mma<<<dim3(N_TOK / 128, NHEAD, BATCH), 128, ATTN_SMEM>>>();

    // 5) output projection + bias -> out
    gemm_mma<0><<<dim3(DIM / 128, M_ROWS / 128), 256, GEMM_SMEM>>>(
        aoh, wph, out, DIM, bproj);
}

// round 15
// speedup vs baseline: 1.0782x; 1.0776x over previous
#include <cuda_runtime.h>
#include <cuda_fp16.h>
#include <cstdint>
#include <cstddef>

// Problem constants
#define BATCH   16
#define N_TOK   1024
#define DIM     512
#define NHEAD   8
#define KHOPS   5
#define HD      64
#define M_ROWS  (BATCH * N_TOK)    // 16384
#define QKV_N   (3 * DIM)          // 1536
#define SCALE_F 0.125f
#define LOG2E   1.4426950408889634f
#define QSCALE  (SCALE_F * LOG2E)   // folded: logits in log2 units

// ---------------------------------------------------------------------------
// Scratch (module-scope device globals; no runtime allocation)
// ---------------------------------------------------------------------------
__device__ __half g_bias[(size_t)NHEAD * N_TOK * N_TOK];  // hop bias * log2e (fp16)
__device__ __half g_xh[(size_t)M_ROWS * DIM];             // x rounded
__device__ __half g_aoh[(size_t)M_ROWS * DIM];            // attn out (fp16)
__device__ __half g_wqh[(size_t)QKV_N * DIM];             // Wqkv rounded
__device__ __half g_wph[(size_t)DIM * DIM];               // Wproj rounded
#define KVSZ ((size_t)BATCH * NHEAD * N_TOK * HD)
__device__ __half g_qh[KVSZ];                   // Q * scale * log2e [bh][tok][64]
__device__ __half g_kh[KVSZ];                   // K                 [bh][tok][64]
__device__ __half g_vth[KVSZ];                  // V^T               [bh][d][tok]

// ---------------------------------------------------------------------------
// helpers
// ---------------------------------------------------------------------------
__device__ __forceinline__ uint32_t ex2h2(float x, float y) {
    __half2 hv = __floats2half2_rn(fminf(x, 14.f), fminf(y, 14.f));
    uint32_t r, in = *reinterpret_cast<uint32_t*>(&hv);
    asm("ex2.approx.f16x2 %0, %1;" : "=r"(r) : "r"(in));
    return r;
}

__device__ __forceinline__ void mma16816(float* c, const uint32_t* a, const uint32_t* b) {
    asm volatile(
        "mma.sync.aligned.m16n8k16.row.col.f32.f16.f16.f32 "
        "{%0,%1,%2,%3}, {%4,%5,%6,%7}, {%8,%9}, {%0,%1,%2,%3};"
        : "+f"(c[0]), "+f"(c[1]), "+f"(c[2]), "+f"(c[3])
        : "r"(a[0]), "r"(a[1]), "r"(a[2]), "r"(a[3]), "r"(b[0]), "r"(b[1]));
}

__device__ __forceinline__ void ldsm4(uint32_t& r0, uint32_t& r1, uint32_t& r2,
                                      uint32_t& r3, uint32_t addr) {
    asm volatile("ldmatrix.sync.aligned.m8n8.x4.shared.b16 {%0,%1,%2,%3}, [%4];"
                 : "=r"(r0), "=r"(r1), "=r"(r2), "=r"(r3) : "r"(addr));
}

__device__ __forceinline__ void cp16(uint32_t dst, const void* src) {
    asm volatile("cp.async.cg.shared.global [%0], [%1], 16;" :: "r"(dst), "l"(src));
}
#define CP_COMMIT() asm volatile("cp.async.commit_group;")
#define CP_WAIT(n)  asm volatile("cp.async.wait_group %0;" :: "n"(n))

// ---------------------------------------------------------------------------
// fused round: fp32 -> fp16 for x | Wqkv | Wproj in one launch
// ---------------------------------------------------------------------------
#define N4_X  (M_ROWS * DIM / 4)
#define N4_WQ (QKV_N * DIM / 4)
#define N4_WP (DIM * DIM / 4)
#define N4_ALL (N4_X + N4_WQ + N4_WP)

__global__ void round_all(const float4* __restrict__ x,
                          const float4* __restrict__ wq,
                          const float4* __restrict__ wp) {
    int i = blockIdx.x * blockDim.x + threadIdx.x;
    if (i >= N4_ALL) return;
    const float4* src;
    uint2* dst;
    int k;
    if (i < N4_X) {
        src = x;  dst = reinterpret_cast<uint2*>(g_xh);  k = i;
    } else if (i < N4_X + N4_WQ) {
        src = wq; dst = reinterpret_cast<uint2*>(g_wqh); k = i - N4_X;
    } else {
        src = wp; dst = reinterpret_cast<uint2*>(g_wph); k = i - N4_X - N4_WQ;
    }
    float4 v = src[k];
    __half2 p0 = __floats2half2_rn(v.x, v.y);
    __half2 p1 = __floats2half2_rn(v.z, v.w);
    dst[k] = make_uint2(*reinterpret_cast<uint32_t*>(&p0), *reinterpret_cast<uint32_t*>(&p1));
}

// ---------------------------------------------------------------------------
// hop-bias precompute -> fp16, pre-multiplied by log2e
// ---------------------------------------------------------------------------
__global__ void bias_kernel(const float* __restrict__ Hstack,
                            const float* __restrict__ hop_logits,
                            const float* __restrict__ rel_alpha) {
    __shared__ float ws[NHEAD][KHOPS];
    if (threadIdx.x == 0) {
        for (int h = 0; h < NHEAD; h++) {
            float mx = -1e30f;
            for (int k = 0; k < KHOPS; k++) mx = fmaxf(mx, hop_logits[h * KHOPS + k]);
            float e[KHOPS]; float s = 0.f;
            for (int k = 0; k < KHOPS; k++) { e[k] = __expf(hop_logits[h * KHOPS + k] - mx); s += e[k]; }
            float a = rel_alpha[h] * LOG2E / s;
            for (int k = 0; k < KHOPS; k++) ws[h][k] = e[k] * a;
        }
    }
    __syncthreads();

    const int total4 = N_TOK * N_TOK / 4;
    int idx = blockIdx.x * blockDim.x + threadIdx.x;
    if (idx >= total4) return;

    float4 hv[KHOPS];
#pragma unroll
    for (int k = 0; k < KHOPS; k++)
        hv[k] = reinterpret_cast<const float4*>(Hstack)[(size_t)k * total4 + idx];

#pragma unroll
    for (int h = 0; h < NHEAD; h++) {
        float4 o = make_float4(0.f, 0.f, 0.f, 0.f);
#pragma unroll
        for (int k = 0; k < KHOPS; k++) {
            float w = ws[h][k];
            o.x += w * hv[k].x; o.y += w * hv[k].y;
            o.z += w * hv[k].z; o.w += w * hv[k].w;
        }
        __half2 p0 = __floats2half2_rn(o.x, o.y);
        __half2 p1 = __floats2half2_rn(o.z, o.w);
        reinterpret_cast<uint2*>(g_bias)[(size_t)h * total4 + idx] =
            make_uint2(*reinterpret_cast<uint32_t*>(&p0), *reinterpret_cast<uint32_t*>(&p1));
    }
}

// ---------------------------------------------------------------------------
// HMMA fp16 GEMM (1-term). MODE 0: fp32 store + bias (proj).
// MODE 1: QKV epilogue -> g_qh/kh/vth. 128x128 tile, BK=32, 4-stage cp.async.
// ---------------------------------------------------------------------------
#define BK  32
#define AKP 40
#define GEMM_SMEM (8 * 128 * AKP * 2)  // 81920 B

template <int MODE>
__global__ __launch_bounds__(256, 2)
void gemm_mma(const __half* __restrict__ Ah, const __half* __restrict__ Wh,
              float* __restrict__ C, int Ncols, const float* __restrict__ biasv) {
    extern __shared__ __half gsm[];
    const int tid = threadIdx.x;
    const int wid = tid >> 5, lane = tid & 31;
    const int g = lane >> 2, t4 = lane & 3;
    const int wm = (wid >> 1) * 32, wn = (wid & 1) * 64;
    const int m0 = blockIdx.y * 128, n0 = blockIdx.x * 128;
    const uint32_t smb = (uint32_t)__cvta_generic_to_shared(gsm);

    const int r0 = tid >> 2,         c0e = (tid & 3) * 8;
    const int r1 = (tid + 256) >> 2, c1e = ((tid + 256) & 3) * 8;

    float acc[2][8][4];
#pragma unroll
    for (int i = 0; i < 2; i++)
#pragma unroll
        for (int j = 0; j < 8; j++)
#pragma unroll
            for (int r = 0; r < 4; r++) acc[i][j][r] = 0.f;

    auto issue = [&](int st, int c) {
        const int k0 = c * BK;
        cp16(smb + 2u * (st * 5120 + r0 * AKP + c0e),
             Ah + (size_t)(m0 + r0) * DIM + k0 + c0e);
        cp16(smb + 2u * (st * 5120 + r1 * AKP + c1e),
             Ah + (size_t)(m0 + r1) * DIM + k0 + c1e);
        cp16(smb + 2u * (20480 + st * 5120 + r0 * AKP + c0e),
             Wh + (size_t)(n0 + r0) * DIM + k0 + c0e);
        cp16(smb + 2u * (20480 + st * 5120 + r1 * AKP + c1e),
             Wh + (size_t)(n0 + r1) * DIM + k0 + c1e);
    };

    issue(0, 0); CP_COMMIT();
    issue(1, 1); CP_COMMIT();
    issue(2, 2); CP_COMMIT();

    const int NCHUNK = 16;
    const int lrow = lane & 15, lcol = (lane >> 4) * 8;

    for (int c = 0; c < NCHUNK; c++) {
        CP_WAIT(2);
        __syncthreads();
        const int st = c & 3;
        const uint32_t abase = smb + 2u * (st * 5120);
        const uint32_t bbase = smb + 2u * (20480 + st * 5120);
#pragma unroll
        for (int kk = 0; kk < BK; kk += 16) {
            uint32_t a[2][4];
#pragma unroll
            for (int i = 0; i < 2; i++)
                ldsm4(a[i][0], a[i][1], a[i][2], a[i][3],
                      abase + 2u * ((wm + i * 16 + lrow) * AKP + kk + lcol));
#pragma unroll
            for (int jb = 0; jb < 4; jb++) {
                uint32_t q0, q1, q2, q3;
                ldsm4(q0, q1, q2, q3,
                      bbase + 2u * ((wn + jb * 16 + lrow) * AKP + kk + lcol));
                uint32_t b0[2] = {q0, q2}, b1[2] = {q1, q3};
                mma16816(acc[0][2 * jb],     a[0], b0);
                mma16816(acc[1][2 * jb],     a[1], b0);
                mma16816(acc[0][2 * jb + 1], a[0], b1);
                mma16816(acc[1][2 * jb + 1], a[1], b1);
            }
        }
        if (c + 3 < NCHUNK) issue((c + 3) & 3, c + 3);
        CP_COMMIT();
    }

    if (MODE == 0) {
#pragma unroll
        for (int i = 0; i < 2; i++) {
#pragma unroll
            for (int j = 0; j < 8; j++) {
                int col = n0 + wn + j * 8 + t4 * 2;
                float bx = biasv[col], by = biasv[col + 1];
                int row0 = m0 + wm + i * 16 + g;
                float2 v0 = make_float2(acc[i][j][0] + bx, acc[i][j][1] + by);
                float2 v1 = make_float2(acc[i][j][2] + bx, acc[i][j][3] + by);
                *reinterpret_cast<float2*>(C + (size_t)row0 * Ncols + col) = v0;
                *reinterpret_cast<float2*>(C + (size_t)(row0 + 8) * Ncols + col) = v1;
            }
        }
    } else {
        const int b = m0 >> 10;
#pragma unroll
        for (int i = 0; i < 2; i++) {
            const int tokA = (m0 & 1023) + wm + i * 16 + g;
            const int tokB = tokA + 8;
#pragma unroll
            for (int j = 0; j < 8; j++) {
                const int col = n0 + wn + j * 8 + t4 * 2;
                if (n0 < 512) {               // ---- Q: scale*log2e + round ----
                    const int hh = col >> 6, d = col & 63;
                    const size_t oA = (((size_t)(b * NHEAD + hh) << 10) + tokA) * HD + d;
                    const size_t oB = (((size_t)(b * NHEAD + hh) << 10) + tokB) * HD + d;
                    __half2 p0 = __floats2half2_rn(acc[i][j][0] * QSCALE, acc[i][j][1] * QSCALE);
                    __half2 p1 = __floats2half2_rn(acc[i][j][2] * QSCALE, acc[i][j][3] * QSCALE);
                    *reinterpret_cast<__half2*>(g_qh + oA) = p0;
                    *reinterpret_cast<__half2*>(g_qh + oB) = p1;
                } else if (n0 < 1024) {       // ---- K: round ----
                    const int c2 = col - 512;
                    const int hh = c2 >> 6, d = c2 & 63;
                    const size_t oA = (((size_t)(b * NHEAD + hh) << 10) + tokA) * HD + d;
                    const size_t oB = (((size_t)(b * NHEAD + hh) << 10) + tokB) * HD + d;
                    __half2 p0 = __floats2half2_rn(acc[i][j][0], acc[i][j][1]);
                    __half2 p1 = __floats2half2_rn(acc[i][j][2], acc[i][j][3]);
                    *reinterpret_cast<__half2*>(g_kh + oA) = p0;
                    *reinterpret_cast<__half2*>(g_kh + oB) = p1;
                } else {                      // ---- V: round + transpose ----
                    const int c2 = col - 1024;
                    const int hh = c2 >> 6, d = c2 & 63;
                    const size_t base = ((size_t)(b * NHEAD + hh) * HD + d) << 10;
                    g_vth[base + tokA]        = __float2half_rn(acc[i][j][0]);
                    g_vth[base + 1024 + tokA] = __float2half_rn(acc[i][j][1]);
                    g_vth[base + tokB]        = __float2half_rn(acc[i][j][2]);
                    g_vth[base + 1024 + tokB] = __float2half_rn(acc[i][j][3]);
                }
            }
        }
    }
}

// ---------------------------------------------------------------------------
// HMMA fp16 flash-attention, fixed-reference log2 softmax.
// 256 thr / 8 warps (16 rows each); K, V AND BIAS all staged through smem
// via double-buffered cp.async (bias LDG latency fully prefetched away).
// Grid (N/128, H, B), 2 CTAs/SM.
// ---------------------------------------------------------------------------
#define QSK 72
#define VSK 72
#define BSK 72
// smem elem offsets: Q | 2 stages of (K 64x72, V 64x72, bias 128x72)
#define QH_OFF 0
#define STAGE_E 18432
#define KOFF(st)  (9216 + (st) * STAGE_E)
#define VTOFF(st) (9216 + (st) * STAGE_E + 4608)
#define BOFF(st)  (9216 + (st) * STAGE_E + 9216)
#define ATTN_SMEM ((9216 + 2 * STAGE_E) * 2)   // 92160 B

__global__ __launch_bounds__(256, 2)
void attn_mma() {
    extern __shared__ __half sb[];
    const int b = blockIdx.z, h = blockIdx.y, r0 = blockIdx.x * 128;
    const int tid = threadIdx.x;
    const int wid = tid >> 5, lane = tid & 31;
    const int g = lane >> 2, t4 = lane & 3;
    const int wm = wid * 16;
    const int bh = b * NHEAD + h;
    const uint32_t smb = (uint32_t)__cvta_generic_to_shared(sb);
    const int lrow = lane & 15, lcol = (lane >> 4) * 8;

    const __half* Qhg  = g_qh  + ((size_t)bh << 10) * HD;
    const __half* Khg  = g_kh  + ((size_t)bh << 10) * HD;
    const __half* Vthg = g_vth + ((size_t)bh * HD << 10);
    const __half* Bg = g_bias + ((size_t)(h * N_TOK + r0)) * N_TOK;

    // Q tile via cp.async (128 x 64)
#pragma unroll
    for (int s = 0; s < 4; s++) {
        const int id = tid + s * 256;
        const int r = id >> 3, c = (id & 7) * 8;
        cp16(smb + 2u * (QH_OFF + r * QSK + c), Qhg + (size_t)(r0 + r) * HD + c);
    }

    auto issue = [&](int st, int c0) {
#pragma unroll
        for (int s = 0; s < 2; s++) {
            const int id = tid + s * 256;
            const int r = id >> 3, c = (id & 7) * 8;
            cp16(smb + 2u * (KOFF(st) + r * QSK + c), Khg + (size_t)(c0 + r) * HD + c);
            cp16(smb + 2u * (VTOFF(st) + r * VSK + c), Vthg + ((size_t)r << 10) + c0 + c);
        }
#pragma unroll
        for (int s = 0; s < 4; s++) {
            const int id = tid + s * 256;
            const int r = id >> 3, c = (id & 7) * 8;   // r 0..127 (8 chunks/row)
            cp16(smb + 2u * (BOFF(st) + r * BSK + c), Bg + (size_t)r * N_TOK + c0 + c);
        }
    };

    issue(0, 0); CP_COMMIT();

    float lacc[4] = {0.f, 0.f, 0.f, 0.f};
    float O[8][4];
#pragma unroll
    for (int j = 0; j < 8; j++)
#pragma unroll
        for (int r = 0; r < 4; r++) O[j][r] = 0.f;

    uint32_t qf[4][4];          // hoisted Q fragments (chunk-invariant)
    const uint32_t ones2[2] = {0x3C003C00u, 0x3C003C00u};

    for (int cc = 0; cc < 16; cc++) {
        if (cc + 1 < 16) { issue((cc + 1) & 1, (cc + 1) * 64); CP_COMMIT(); CP_WAIT(1); }
        else             { CP_WAIT(0); }
        __syncthreads();
        const int st = cc & 1;

        if (cc == 0) {
#pragma unroll
            for (int kt = 0; kt < 4; kt++)
                ldsm4(qf[kt][0], qf[kt][1], qf[kt][2], qf[kt][3],
                      smb + 2u * (QH_OFF + (wm + lrow) * QSK + kt * 16 + lcol));
        }

        // ---- S = Qh Kh^T  (log2 units) ----
        float S[8][4];
#pragma unroll
        for (int j = 0; j < 8; j++)
#pragma unroll
            for (int r = 0; r < 4; r++) S[j][r] = 0.f;

#pragma unroll
        for (int kt = 0; kt < 4; kt++) {
#pragma unroll
            for (int jb = 0; jb < 4; jb++) {
                uint32_t q0, q1, q2, q3;
                ldsm4(q0, q1, q2, q3,
                      smb + 2u * (KOFF(st) + (jb * 16 + lrow) * QSK + kt * 16 + lcol));
                uint32_t b0[2] = {q0, q2}, b1[2] = {q1, q3};
                mma16816(S[2 * jb],     qf[kt], b0);
                mma16816(S[2 * jb + 1], qf[kt], b1);
            }
        }

        // ---- + bias from smem (prefetched via cp.async, LDS only) ----
        {
            const __half* bs = sb + BOFF(st);
#pragma unroll
            for (int j = 0; j < 8; j++) {
                const int cix = j * 8 + t4 * 2;
                float2 v0 = __half22float2(
                    *reinterpret_cast<const __half2*>(bs + (wm + g) * BSK + cix));
                float2 v1 = __half22float2(
                    *reinterpret_cast<const __half2*>(bs + (wm + g + 8) * BSK + cix));
                S[j][0] += v0.x; S[j][1] += v0.y;
                S[j][2] += v1.x; S[j][3] += v1.y;
            }
        }

        // ---- P = ex2(S) fp16; l += P*1; O += P*Vh ----
#pragma unroll
        for (int kt = 0; kt < 4; kt++) {
            uint32_t ph[4];
            ph[0] = ex2h2(S[2 * kt][0],     S[2 * kt][1]);
            ph[1] = ex2h2(S[2 * kt][2],     S[2 * kt][3]);
            ph[2] = ex2h2(S[2 * kt + 1][0], S[2 * kt + 1][1]);
            ph[3] = ex2h2(S[2 * kt + 1][2], S[2 * kt + 1][3]);
            mma16816(lacc, ph, ones2);
#pragma unroll
            for (int jb = 0; jb < 4; jb++) {
                uint32_t h0, h1, h2, h3;
                ldsm4(h0, h1, h2, h3,
                      smb + 2u * (VTOFF(st) + (jb * 16 + lrow) * VSK + kt * 16 + lcol));
                uint32_t bh0[2] = {h0, h2}, bh1[2] = {h1, h3};
                mma16816(O[2 * jb],     ph, bh0);
                mma16816(O[2 * jb + 1], ph, bh1);
            }
        }
        __syncthreads();
    }

    // ---- normalize + write fp16 proj operand ----
    float inv0 = 1.0f / lacc[0], inv1 = 1.0f / lacc[2];
    const int row = r0 + wm + g;
    size_t base0 = ((size_t)(b * N_TOK) + row) * DIM + h * HD;
    size_t base1 = base0 + (size_t)8 * DIM;
#pragma unroll
    for (int j = 0; j < 8; j++) {
        const int col = j * 8 + t4 * 2;
        __half2 v0 = __floats2half2_rn(O[j][0] * inv0, O[j][1] * inv0);
        __half2 v1 = __floats2half2_rn(O[j][2] * inv1, O[j][3] * inv1);
        *reinterpret_cast<__half2*>(g_aoh + base0 + col) = v0;
        *reinterpret_cast<__half2*>(g_aoh + base1 + col) = v1;
    }
}

// ---------------------------------------------------------------------------
// Launch
// ---------------------------------------------------------------------------
extern "C" void kernel_launch(void* const* d_in, const int* in_sizes, int n_in,
                              void* d_out, int out_size) {
    const float* x          = (const float*)d_in[0];
    const float* Hstack     = (const float*)d_in[1];
    const float* hop_logits = (const float*)d_in[2];
    const float* rel_alpha  = (const float*)d_in[3];
    const float* Wqkv       = (const float*)d_in[4];
    const float* Wproj      = (const float*)d_in[5];
    const float* bproj      = (const float*)d_in[6];
    float* out = (float*)d_out;

    __half *xh, *aoh, *wqh, *wph;
    cudaGetSymbolAddress((void**)&xh, g_xh);
    cudaGetSymbolAddress((void**)&aoh, g_aoh);
    cudaGetSymbolAddress((void**)&wqh, g_wqh);
    cudaGetSymbolAddress((void**)&wph, g_wph);

    static bool attr_done = false;
    if (!attr_done) {
        cudaFuncSetAttribute(attn_mma, cudaFuncAttributeMaxDynamicSharedMemorySize, ATTN_SMEM);
        cudaFuncSetAttribute((const void*)gemm_mma<0>, cudaFuncAttributeMaxDynamicSharedMemorySize, GEMM_SMEM);
        cudaFuncSetAttribute((const void*)gemm_mma<1>, cudaFuncAttributeMaxDynamicSharedMemorySize, GEMM_SMEM);
        attr_done = true;
    }

    // 1) hop bias (fp16, *log2e)
    bias_kernel<<<(N_TOK * N_TOK / 4 + 255) / 256, 256>>>(Hstack, hop_logits, rel_alpha);

    // 2) round all operands to fp16 (single fused launch)
    round_all<<<(N4_ALL + 255) / 256, 256>>>(
        (const float4*)x, (const float4*)Wqkv, (const float4*)Wproj);

    // 3) QKV projection with fused attention-prep epilogue
    gemm_mma<1><<<dim3(QKV_N / 128, M_ROWS / 128), 256, GEMM_SMEM>>>(
        xh, wqh, nullptr, QKV_N, nullptr);

    // 4) fp16 flash attention (smem-staged bias) -> g_aoh
    attn_mma<<<dim3(N_TOK / 128, NHEAD, BATCH), 256, ATTN_SMEM>>>();

    // 5) output projection + bias -> out
    gemm_mma<0><<<dim3(DIM / 128, M_ROWS / 128), 256, GEMM_SMEM>>>(
        aoh, wph, out, DIM, bproj);
}

// round 16
// speedup vs baseline: 1.1240x; 1.0424x over previous
#include <cuda_runtime.h>
#include <cuda_fp16.h>
#include <cstdint>
#include <cstddef>

// Problem constants
#define BATCH   16
#define N_TOK   1024
#define DIM     512
#define NHEAD   8
#define KHOPS   5
#define HD      64
#define M_ROWS  (BATCH * N_TOK)    // 16384
#define QKV_N   (3 * DIM)          // 1536
#define SCALE_F 0.125f
#define LOG2E   1.4426950408889634f
#define QSCALE  (SCALE_F * LOG2E)   // folded: logits in log2 units

// ---------------------------------------------------------------------------
// Scratch (module-scope device globals; no runtime allocation)
// ---------------------------------------------------------------------------
__device__ __half g_bias[(size_t)NHEAD * N_TOK * N_TOK];  // hop bias * log2e (fp16)
__device__ __half g_xh[(size_t)M_ROWS * DIM];             // x rounded
__device__ __half g_aoh[(size_t)M_ROWS * DIM];            // attn out (fp16)
__device__ __half g_wqh[(size_t)QKV_N * DIM];             // Wqkv rounded
__device__ __half g_wph[(size_t)DIM * DIM];               // Wproj rounded
#define KVSZ ((size_t)BATCH * NHEAD * N_TOK * HD)
__device__ __half g_qh[KVSZ];                   // Q * scale * log2e [bh][tok][64]
__device__ __half g_kh[KVSZ];                   // K                 [bh][tok][64]
__device__ __half g_vth[KVSZ];                  // V^T               [bh][d][tok]

// ---------------------------------------------------------------------------
// helpers
// ---------------------------------------------------------------------------
__device__ __forceinline__ uint32_t packh2(float x, float y) {
    __half2 h = __floats2half2_rn(x, y);
    return *reinterpret_cast<uint32_t*>(&h);
}
__device__ __forceinline__ uint32_t hadd2u(uint32_t a, uint32_t b) {
    uint32_t r; asm("add.f16x2 %0, %1, %2;" : "=r"(r) : "r"(a), "r"(b)); return r;
}
__device__ __forceinline__ uint32_t hmin2u(uint32_t a, uint32_t b) {
    uint32_t r; asm("min.f16x2 %0, %1, %2;" : "=r"(r) : "r"(a), "r"(b)); return r;
}
__device__ __forceinline__ uint32_t ex2u(uint32_t v) {
    uint32_t r; asm("ex2.approx.f16x2 %0, %1;" : "=r"(r) : "r"(v)); return r;
}

__device__ __forceinline__ void mma16816(float* c, const uint32_t* a, const uint32_t* b) {
    asm volatile(
        "mma.sync.aligned.m16n8k16.row.col.f32.f16.f16.f32 "
        "{%0,%1,%2,%3}, {%4,%5,%6,%7}, {%8,%9}, {%0,%1,%2,%3};"
        : "+f"(c[0]), "+f"(c[1]), "+f"(c[2]), "+f"(c[3])
        : "r"(a[0]), "r"(a[1]), "r"(a[2]), "r"(a[3]), "r"(b[0]), "r"(b[1]));
}

__device__ __forceinline__ void ldsm4(uint32_t& r0, uint32_t& r1, uint32_t& r2,
                                      uint32_t& r3, uint32_t addr) {
    asm volatile("ldmatrix.sync.aligned.m8n8.x4.shared.b16 {%0,%1,%2,%3}, [%4];"
                 : "=r"(r0), "=r"(r1), "=r"(r2), "=r"(r3) : "r"(addr));
}

__device__ __forceinline__ void cp16(uint32_t dst, const void* src) {
    asm volatile("cp.async.cg.shared.global [%0], [%1], 16;" :: "r"(dst), "l"(src));
}
#define CP_COMMIT() asm volatile("cp.async.commit_group;")
#define CP_WAIT(n)  asm volatile("cp.async.wait_group %0;" :: "n"(n))

// ---------------------------------------------------------------------------
// fused round: fp32 -> fp16 for x | Wqkv | Wproj in one launch
// ---------------------------------------------------------------------------
#define N4_X  (M_ROWS * DIM / 4)
#define N4_WQ (QKV_N * DIM / 4)
#define N4_WP (DIM * DIM / 4)
#define N4_ALL (N4_X + N4_WQ + N4_WP)

__global__ void round_all(const float4* __restrict__ x,
                          const float4* __restrict__ wq,
                          const float4* __restrict__ wp) {
    int i = blockIdx.x * blockDim.x + threadIdx.x;
    if (i >= N4_ALL) return;
    const float4* src;
    uint2* dst;
    int k;
    if (i < N4_X) {
        src = x;  dst = reinterpret_cast<uint2*>(g_xh);  k = i;
    } else if (i < N4_X + N4_WQ) {
        src = wq; dst = reinterpret_cast<uint2*>(g_wqh); k = i - N4_X;
    } else {
        src = wp; dst = reinterpret_cast<uint2*>(g_wph); k = i - N4_X - N4_WQ;
    }
    float4 v = src[k];
    dst[k] = make_uint2(packh2(v.x, v.y), packh2(v.z, v.w));
}

// ---------------------------------------------------------------------------
// hop-bias precompute -> fp16, pre-multiplied by log2e
// ---------------------------------------------------------------------------
__global__ void bias_kernel(const float* __restrict__ Hstack,
                            const float* __restrict__ hop_logits,
                            const float* __restrict__ rel_alpha) {
    __shared__ float ws[NHEAD][KHOPS];
    if (threadIdx.x == 0) {
        for (int h = 0; h < NHEAD; h++) {
            float mx = -1e30f;
            for (int k = 0; k < KHOPS; k++) mx = fmaxf(mx, hop_logits[h * KHOPS + k]);
            float e[KHOPS]; float s = 0.f;
            for (int k = 0; k < KHOPS; k++) { e[k] = __expf(hop_logits[h * KHOPS + k] - mx); s += e[k]; }
            float a = rel_alpha[h] * LOG2E / s;
            for (int k = 0; k < KHOPS; k++) ws[h][k] = e[k] * a;
        }
    }
    __syncthreads();

    const int total4 = N_TOK * N_TOK / 4;
    int idx = blockIdx.x * blockDim.x + threadIdx.x;
    if (idx >= total4) return;

    float4 hv[KHOPS];
#pragma unroll
    for (int k = 0; k < KHOPS; k++)
        hv[k] = reinterpret_cast<const float4*>(Hstack)[(size_t)k * total4 + idx];

#pragma unroll
    for (int h = 0; h < NHEAD; h++) {
        float4 o = make_float4(0.f, 0.f, 0.f, 0.f);
#pragma unroll
        for (int k = 0; k < KHOPS; k++) {
            float w = ws[h][k];
            o.x += w * hv[k].x; o.y += w * hv[k].y;
            o.z += w * hv[k].z; o.w += w * hv[k].w;
        }
        reinterpret_cast<uint2*>(g_bias)[(size_t)h * total4 + idx] =
            make_uint2(packh2(o.x, o.y), packh2(o.z, o.w));
    }
}

// ---------------------------------------------------------------------------
// HMMA fp16 GEMM (1-term). MODE 0: fp32 store + bias (proj).
// MODE 1: QKV epilogue -> g_qh/kh/vth. 128x128 tile, BK=32, 4-stage cp.async.
// ---------------------------------------------------------------------------
#define BK  32
#define AKP 40
#define GEMM_SMEM (8 * 128 * AKP * 2)  // 81920 B

template <int MODE>
__global__ __launch_bounds__(256, 2)
void gemm_mma(const __half* __restrict__ Ah, const __half* __restrict__ Wh,
              float* __restrict__ C, int Ncols, const float* __restrict__ biasv) {
    extern __shared__ __half gsm[];
    const int tid = threadIdx.x;
    const int wid = tid >> 5, lane = tid & 31;
    const int g = lane >> 2, t4 = lane & 3;
    const int wm = (wid >> 1) * 32, wn = (wid & 1) * 64;
    const int m0 = blockIdx.y * 128, n0 = blockIdx.x * 128;
    const uint32_t smb = (uint32_t)__cvta_generic_to_shared(gsm);

    const int r0 = tid >> 2,         c0e = (tid & 3) * 8;
    const int r1 = (tid + 256) >> 2, c1e = ((tid + 256) & 3) * 8;

    float acc[2][8][4];
#pragma unroll
    for (int i = 0; i < 2; i++)
#pragma unroll
        for (int j = 0; j < 8; j++)
#pragma unroll
            for (int r = 0; r < 4; r++) acc[i][j][r] = 0.f;

    auto issue = [&](int st, int c) {
        const int k0 = c * BK;
        cp16(smb + 2u * (st * 5120 + r0 * AKP + c0e),
             Ah + (size_t)(m0 + r0) * DIM + k0 + c0e);
        cp16(smb + 2u * (st * 5120 + r1 * AKP + c1e),
             Ah + (size_t)(m0 + r1) * DIM + k0 + c1e);
        cp16(smb + 2u * (20480 + st * 5120 + r0 * AKP + c0e),
             Wh + (size_t)(n0 + r0) * DIM + k0 + c0e);
        cp16(smb + 2u * (20480 + st * 5120 + r1 * AKP + c1e),
             Wh + (size_t)(n0 + r1) * DIM + k0 + c1e);
    };

    issue(0, 0); CP_COMMIT();
    issue(1, 1); CP_COMMIT();
    issue(2, 2); CP_COMMIT();

    const int NCHUNK = 16;
    const int lrow = lane & 15, lcol = (lane >> 4) * 8;

    for (int c = 0; c < NCHUNK; c++) {
        CP_WAIT(2);
        __syncthreads();
        const int st = c & 3;
        const uint32_t abase = smb + 2u * (st * 5120);
        const uint32_t bbase = smb + 2u * (20480 + st * 5120);
#pragma unroll
        for (int kk = 0; kk < BK; kk += 16) {
            uint32_t a[2][4];
#pragma unroll
            for (int i = 0; i < 2; i++)
                ldsm4(a[i][0], a[i][1], a[i][2], a[i][3],
                      abase + 2u * ((wm + i * 16 + lrow) * AKP + kk + lcol));
#pragma unroll
            for (int jb = 0; jb < 4; jb++) {
                uint32_t q0, q1, q2, q3;
                ldsm4(q0, q1, q2, q3,
                      bbase + 2u * ((wn + jb * 16 + lrow) * AKP + kk + lcol));
                uint32_t b0[2] = {q0, q2}, b1[2] = {q1, q3};
                mma16816(acc[0][2 * jb],     a[0], b0);
                mma16816(acc[1][2 * jb],     a[1], b0);
                mma16816(acc[0][2 * jb + 1], a[0], b1);
                mma16816(acc[1][2 * jb + 1], a[1], b1);
            }
        }
        if (c + 3 < NCHUNK) issue((c + 3) & 3, c + 3);
        CP_COMMIT();
    }

    if (MODE == 0) {
#pragma unroll
        for (int i = 0; i < 2; i++) {
#pragma unroll
            for (int j = 0; j < 8; j++) {
                int col = n0 + wn + j * 8 + t4 * 2;
                float bx = biasv[col], by = biasv[col + 1];
                int row0 = m0 + wm + i * 16 + g;
                float2 v0 = make_float2(acc[i][j][0] + bx, acc[i][j][1] + by);
                float2 v1 = make_float2(acc[i][j][2] + bx, acc[i][j][3] + by);
                *reinterpret_cast<float2*>(C + (size_t)row0 * Ncols + col) = v0;
                *reinterpret_cast<float2*>(C + (size_t)(row0 + 8) * Ncols + col) = v1;
            }
        }
    } else {
        const int b = m0 >> 10;
#pragma unroll
        for (int i = 0; i < 2; i++) {
            const int tokA = (m0 & 1023) + wm + i * 16 + g;
            const int tokB = tokA + 8;
#pragma unroll
            for (int j = 0; j < 8; j++) {
                const int col = n0 + wn + j * 8 + t4 * 2;
                if (n0 < 512) {               // ---- Q: scale*log2e + round ----
                    const int hh = col >> 6, d = col & 63;
                    const size_t oA = (((size_t)(b * NHEAD + hh) << 10) + tokA) * HD + d;
                    const size_t oB = (((size_t)(b * NHEAD + hh) << 10) + tokB) * HD + d;
                    *reinterpret_cast<uint32_t*>(g_qh + oA) =
                        packh2(acc[i][j][0] * QSCALE, acc[i][j][1] * QSCALE);
                    *reinterpret_cast<uint32_t*>(g_qh + oB) =
                        packh2(acc[i][j][2] * QSCALE, acc[i][j][3] * QSCALE);
                } else if (n0 < 1024) {       // ---- K: round ----
                    const int c2 = col - 512;
                    const int hh = c2 >> 6, d = c2 & 63;
                    const size_t oA = (((size_t)(b * NHEAD + hh) << 10) + tokA) * HD + d;
                    const size_t oB = (((size_t)(b * NHEAD + hh) << 10) + tokB) * HD + d;
                    *reinterpret_cast<uint32_t*>(g_kh + oA) = packh2(acc[i][j][0], acc[i][j][1]);
                    *reinterpret_cast<uint32_t*>(g_kh + oB) = packh2(acc[i][j][2], acc[i][j][3]);
                } else {                      // ---- V: round + transpose ----
                    const int c2 = col - 1024;
                    const int hh = c2 >> 6, d = c2 & 63;
                    const size_t base = ((size_t)(b * NHEAD + hh) * HD + d) << 10;
                    g_vth[base + tokA]        = __float2half_rn(acc[i][j][0]);
                    g_vth[base + 1024 + tokA] = __float2half_rn(acc[i][j][1]);
                    g_vth[base + tokB]        = __float2half_rn(acc[i][j][2]);
                    g_vth[base + 1024 + tokB] = __float2half_rn(acc[i][j][3]);
                }
            }
        }
    }
}

// ---------------------------------------------------------------------------
// HMMA fp16 flash-attention, fixed-reference log2 softmax.
// Single barrier per chunk; bias add + clamp + exp entirely in fp16x2.
// 256 thr / 8 warps; K, V, bias staged via double-buffered cp.async.
// Grid (N/128, H, B), 2 CTAs/SM.
// ---------------------------------------------------------------------------
#define QSK 72
#define VSK 72
#define BSK 72
#define QH_OFF 0
#define STAGE_E 18432
#define KOFF(st)  (9216 + (st) * STAGE_E)
#define VTOFF(st) (9216 + (st) * STAGE_E + 4608)
#define BOFF(st)  (9216 + (st) * STAGE_E + 9216)
#define ATTN_SMEM ((9216 + 2 * STAGE_E) * 2)   // 92160 B
#define C14H2 0x4B004B00u   // fp16x2 {14.0, 14.0}

__global__ __launch_bounds__(256, 2)
void attn_mma() {
    extern __shared__ __half sb[];
    const int b = blockIdx.z, h = blockIdx.y, r0 = blockIdx.x * 128;
    const int tid = threadIdx.x;
    const int wid = tid >> 5, lane = tid & 31;
    const int g = lane >> 2, t4 = lane & 3;
    const int wm = wid * 16;
    const int bh = b * NHEAD + h;
    const uint32_t smb = (uint32_t)__cvta_generic_to_shared(sb);
    const int lrow = lane & 15, lcol = (lane >> 4) * 8;

    const __half* Qhg  = g_qh  + ((size_t)bh << 10) * HD;
    const __half* Khg  = g_kh  + ((size_t)bh << 10) * HD;
    const __half* Vthg = g_vth + ((size_t)bh * HD << 10);
    const __half* Bg = g_bias + ((size_t)(h * N_TOK + r0)) * N_TOK;

    // Q tile via cp.async (128 x 64)
#pragma unroll
    for (int s = 0; s < 4; s++) {
        const int id = tid + s * 256;
        const int r = id >> 3, c = (id & 7) * 8;
        cp16(smb + 2u * (QH_OFF + r * QSK + c), Qhg + (size_t)(r0 + r) * HD + c);
    }

    auto issue = [&](int st, int c0) {
#pragma unroll
        for (int s = 0; s < 2; s++) {
            const int id = tid + s * 256;
            const int r = id >> 3, c = (id & 7) * 8;
            cp16(smb + 2u * (KOFF(st) + r * QSK + c), Khg + (size_t)(c0 + r) * HD + c);
            cp16(smb + 2u * (VTOFF(st) + r * VSK + c), Vthg + ((size_t)r << 10) + c0 + c);
        }
#pragma unroll
        for (int s = 0; s < 4; s++) {
            const int id = tid + s * 256;
            const int r = id >> 3, c = (id & 7) * 8;
            cp16(smb + 2u * (BOFF(st) + r * BSK + c), Bg + (size_t)r * N_TOK + c0 + c);
        }
    };

    issue(0, 0); CP_COMMIT();

    float lacc[4] = {0.f, 0.f, 0.f, 0.f};
    float O[8][4];
#pragma unroll
    for (int j = 0; j < 8; j++)
#pragma unroll
        for (int r = 0; r < 4; r++) O[j][r] = 0.f;

    uint32_t qf[4][4];          // hoisted Q fragments (chunk-invariant)
    const uint32_t ones2[2] = {0x3C003C00u, 0x3C003C00u};

    for (int cc = 0; cc < 16; cc++) {
        CP_WAIT(0);
        __syncthreads();        // single barrier: data-ready + readers-done
        if (cc + 1 < 16) { issue((cc + 1) & 1, (cc + 1) * 64); CP_COMMIT(); }
        const int st = cc & 1;

        if (cc == 0) {
#pragma unroll
            for (int kt = 0; kt < 4; kt++)
                ldsm4(qf[kt][0], qf[kt][1], qf[kt][2], qf[kt][3],
                      smb + 2u * (QH_OFF + (wm + lrow) * QSK + kt * 16 + lcol));
        }

        // ---- S = Qh Kh^T  (log2 units) ----
        float S[8][4];
#pragma unroll
        for (int j = 0; j < 8; j++)
#pragma unroll
            for (int r = 0; r < 4; r++) S[j][r] = 0.f;

#pragma unroll
        for (int kt = 0; kt < 4; kt++) {
#pragma unroll
            for (int jb = 0; jb < 4; jb++) {
                uint32_t q0, q1, q2, q3;
                ldsm4(q0, q1, q2, q3,
                      smb + 2u * (KOFF(st) + (jb * 16 + lrow) * QSK + kt * 16 + lcol));
                uint32_t b0[2] = {q0, q2}, b1[2] = {q1, q3};
                mma16816(S[2 * jb],     qf[kt], b0);
                mma16816(S[2 * jb + 1], qf[kt], b1);
            }
        }

        // ---- fp16 path: P = ex2(min(pack(S) + bias, 14)); l += P*1; O += P*Vh ----
        const uint32_t* bwA = reinterpret_cast<const uint32_t*>(sb + BOFF(st))
                            + (wm + g) * (BSK / 2) + t4;
        const uint32_t* bwB = bwA + 8 * (BSK / 2);
#pragma unroll
        for (int kt = 0; kt < 4; kt++) {
            uint32_t ph[4];
            ph[0] = ex2u(hmin2u(hadd2u(packh2(S[2 * kt][0],     S[2 * kt][1]),     bwA[8 * kt]),     C14H2));
            ph[1] = ex2u(hmin2u(hadd2u(packh2(S[2 * kt][2],     S[2 * kt][3]),     bwB[8 * kt]),     C14H2));
            ph[2] = ex2u(hmin2u(hadd2u(packh2(S[2 * kt + 1][0], S[2 * kt + 1][1]), bwA[8 * kt + 4]), C14H2));
            ph[3] = ex2u(hmin2u(hadd2u(packh2(S[2 * kt + 1][2], S[2 * kt + 1][3]), bwB[8 * kt + 4]), C14H2));
            mma16816(lacc, ph, ones2);
#pragma unroll
            for (int jb = 0; jb < 4; jb++) {
                uint32_t h0, h1, h2, h3;
                ldsm4(h0, h1, h2, h3,
                      smb + 2u * (VTOFF(st) + (jb * 16 + lrow) * VSK + kt * 16 + lcol));
                uint32_t bh0[2] = {h0, h2}, bh1[2] = {h1, h3};
                mma16816(O[2 * jb],     ph, bh0);
                mma16816(O[2 * jb + 1], ph, bh1);
            }
        }
    }

    // ---- normalize + write fp16 proj operand ----
    float inv0 = 1.0f / lacc[0], inv1 = 1.0f / lacc[2];
    const int row = r0 + wm + g;
    size_t base0 = ((size_t)(b * N_TOK) + row) * DIM + h * HD;
    size_t base1 = base0 + (size_t)8 * DIM;
#pragma unroll
    for (int j = 0; j < 8; j++) {
        const int col = j * 8 + t4 * 2;
        *reinterpret_cast<uint32_t*>(g_aoh + base0 + col) = packh2(O[j][0] * inv0, O[j][1] * inv0);
        *reinterpret_cast<uint32_t*>(g_aoh + base1 + col) = packh2(O[j][2] * inv1, O[j][3] * inv1);
    }
}

// ---------------------------------------------------------------------------
// Launch
// ---------------------------------------------------------------------------
extern "C" void kernel_launch(void* const* d_in, const int* in_sizes, int n_in,
                              void* d_out, int out_size) {
    const float* x          = (const float*)d_in[0];
    const float* Hstack     = (const float*)d_in[1];
    const float* hop_logits = (const float*)d_in[2];
    const float* rel_alpha  = (const float*)d_in[3];
    const float* Wqkv       = (const float*)d_in[4];
    const float* Wproj      = (const float*)d_in[5];
    const float* bproj      = (const float*)d_in[6];
    float* out = (float*)d_out;

    __half *xh, *aoh, *wqh, *wph;
    cudaGetSymbolAddress((void**)&xh, g_xh);
    cudaGetSymbolAddress((void**)&aoh, g_aoh);
    cudaGetSymbolAddress((void**)&wqh, g_wqh);
    cudaGetSymbolAddress((void**)&wph, g_wph);

    static bool attr_done = false;
    if (!attr_done) {
        cudaFuncSetAttribute(attn_mma, cudaFuncAttributeMaxDynamicSharedMemorySize, ATTN_SMEM);
        cudaFuncSetAttribute((const void*)gemm_mma<0>, cudaFuncAttributeMaxDynamicSharedMemorySize, GEMM_SMEM);
        cudaFuncSetAttribute((const void*)gemm_mma<1>, cudaFuncAttributeMaxDynamicSharedMemorySize, GEMM_SMEM);
        attr_done = true;
    }

    // 1) hop bias (fp16, *log2e)
    bias_kernel<<<(N_TOK * N_TOK / 4 + 255) / 256, 256>>>(Hstack, hop_logits, rel_alpha);

    // 2) round all operands to fp16 (single fused launch)
    round_all<<<(N4_ALL + 255) / 256, 256>>>(
        (const float4*)x, (const float4*)Wqkv, (const float4*)Wproj);

    // 3) QKV projection with fused attention-prep epilogue
    gemm_mma<1><<<dim3(QKV_N / 128, M_ROWS / 128), 256, GEMM_SMEM>>>(
        xh, wqh, nullptr, QKV_N, nullptr);

    // 4) fp16 flash attention (smem bias, fp16 softmax path) -> g_aoh
    attn_mma<<<dim3(N_TOK / 128, NHEAD, BATCH), 256, ATTN_SMEM>>>();

    // 5) output projection + bias -> out
    gemm_mma<0><<<dim3(DIM / 128, M_ROWS / 128), 256, GEMM_SMEM>>>(
        aoh, wph, out, DIM, bproj);
}